// round 2
// baseline (speedup 1.0000x reference)
#include <cuda_runtime.h>
#include <math.h>

#define NMAX 100000
#define EMAX 1600000
#define HHEADS 8
#define CCH 8
#define FEAT 128
#define OUTD 64   // H*C

// ---------------- device scratch (no allocations allowed) ----------------
__device__ float g_h[NMAX * OUTD];     // transformed features  [N,64]
__device__ float g_as[NMAX * HHEADS];  // a_src  [N,8]
__device__ float g_ad[NMAX * HHEADS];  // a_dst  [N,8]
__device__ float g_m[NMAX * HHEADS];   // segment max  [N,8]
__device__ float g_den[NMAX * HHEADS]; // segment sum  [N,8]

// ---------------- helpers ----------------
__device__ __forceinline__ void atomicMaxF(float* addr, float v) {
    // sign-routed trick: works for mixed-sign values with -inf init
    if (v >= 0.0f) {
        atomicMax((int*)addr, __float_as_int(v));
    } else {
        atomicMin((unsigned int*)addr, __float_as_uint(v));
    }
}

__device__ __forceinline__ void redAddV4(float* addr, float a, float b, float c, float d) {
    asm volatile("red.global.add.v4.f32 [%0], {%1, %2, %3, %4};"
                 :: "l"(addr), "f"(a), "f"(b), "f"(c), "f"(d) : "memory");
}

// ---------------- kernel 1: GEMM + attention logits + init ----------------
// 128 threads per block, 16 nodes per block, 8 threads per node (one head each).
__global__ void k1_gemm_att(const float* __restrict__ x,
                            const float* __restrict__ W,
                            const float* __restrict__ att_s,
                            const float* __restrict__ att_d,
                            float* __restrict__ out,
                            int N) {
    __shared__ float Ws[FEAT * OUTD];     // 32 KB
    __shared__ float xs[16][FEAT + 1];    // padded rows to avoid bank conflicts

    int t = threadIdx.x; // 0..127
    // cooperative load of W (128x64 row-major), float4-coalesced
    const float4* W4 = (const float4*)W;
    float4* Ws4 = (float4*)Ws;
    #pragma unroll
    for (int i = 0; i < 16; i++) {
        Ws4[t + 128 * i] = W4[t + 128 * i];
    }
    int node0 = blockIdx.x * 16;
    // stage 16 x-rows
    for (int i = t; i < 16 * FEAT; i += 128) {
        int nn = i >> 7;
        int kk = i & 127;
        int gn = node0 + nn;
        xs[nn][kk] = (gn < N) ? x[(long)gn * FEAT + kk] : 0.0f;
    }
    __syncthreads();

    int node = t >> 3;
    int head = t & 7;
    int gn = node0 + node;
    if (gn >= N) return;

    float acc[8];
    #pragma unroll
    for (int c = 0; c < 8; c++) acc[c] = 0.0f;

    const float* xrow = xs[node];
    #pragma unroll 4
    for (int k = 0; k < FEAT; k++) {
        float xv = xrow[k];
        const float4 w0 = *(const float4*)&Ws[k * OUTD + head * 8];
        const float4 w1 = *(const float4*)&Ws[k * OUTD + head * 8 + 4];
        acc[0] = fmaf(xv, w0.x, acc[0]);
        acc[1] = fmaf(xv, w0.y, acc[1]);
        acc[2] = fmaf(xv, w0.z, acc[2]);
        acc[3] = fmaf(xv, w0.w, acc[3]);
        acc[4] = fmaf(xv, w1.x, acc[4]);
        acc[5] = fmaf(xv, w1.y, acc[5]);
        acc[6] = fmaf(xv, w1.z, acc[6]);
        acc[7] = fmaf(xv, w1.w, acc[7]);
    }

    // attention logits for this (node, head)
    float as = 0.0f, ad = 0.0f;
    #pragma unroll
    for (int c = 0; c < 8; c++) {
        as = fmaf(acc[c], __ldg(&att_s[head * 8 + c]), as);
        ad = fmaf(acc[c], __ldg(&att_d[head * 8 + c]), ad);
    }

    long base = (long)gn * OUTD + head * 8;
    *(float4*)&g_h[base]     = make_float4(acc[0], acc[1], acc[2], acc[3]);
    *(float4*)&g_h[base + 4] = make_float4(acc[4], acc[5], acc[6], acc[7]);
    g_as[gn * HHEADS + head] = as;
    g_ad[gn * HHEADS + head] = ad;
    g_m[gn * HHEADS + head] = -INFINITY;
    g_den[gn * HHEADS + head] = 0.0f;
    // zero the output accumulator (d_out is poisoned)
    float4 z = make_float4(0.f, 0.f, 0.f, 0.f);
    *(float4*)&out[base] = z;
    *(float4*)&out[base + 4] = z;
}

// ---------------- kernel 2: segment max over edges ----------------
// 1 thread per edge (incl. self-loops: edge id >= E -> s=d=id-E)
__global__ void k2_max(const int* __restrict__ ei, int E, int Etot) {
    int t = blockIdx.x * blockDim.x + threadIdx.x;
    if (t >= Etot) return;
    int s, d;
    if (t < E) {
        s = __ldg(&ei[t]);
        d = __ldg(&ei[E + t]);
    } else {
        s = d = t - E;
    }
    float4 as0 = *(const float4*)&g_as[s * HHEADS];
    float4 as1 = *(const float4*)&g_as[s * HHEADS + 4];
    float4 ad0 = *(const float4*)&g_ad[d * HHEADS];
    float4 ad1 = *(const float4*)&g_ad[d * HHEADS + 4];
    float e[8] = {as0.x + ad0.x, as0.y + ad0.y, as0.z + ad0.z, as0.w + ad0.w,
                  as1.x + ad1.x, as1.y + ad1.y, as1.z + ad1.z, as1.w + ad1.w};
    #pragma unroll
    for (int h = 0; h < 8; h++) {
        float v = e[h];
        v = (v > 0.0f) ? v : 0.2f * v;
        atomicMaxF(&g_m[d * HHEADS + h], v);
    }
}

// ---------------- kernel 3: exp + denom + unnormalized message scatter ----------------
// 16 lanes (half-warp) per edge; 256 threads -> 16 edges per block.
__global__ void k3_accum(const int* __restrict__ ei,
                         float* __restrict__ out,
                         int E, int Etot) {
    int t = threadIdx.x;
    int eid = blockIdx.x * 16 + (t >> 4);
    bool valid = (eid < Etot);
    int s = 0, d = 0;
    if (valid) {
        if (eid < E) {
            s = __ldg(&ei[eid]);
            d = __ldg(&ei[E + eid]);
        } else {
            s = d = eid - E;
        }
    }
    int q = t & 15;
    float ex = 0.0f;
    if (valid && q < 8) {
        float e = g_as[s * HHEADS + q] + g_ad[d * HHEADS + q];
        e = (e > 0.0f) ? e : 0.2f * e;
        ex = __expf(e - g_m[d * HHEADS + q]);
        atomicAdd(&g_den[d * HHEADS + q], ex);
    }
    // broadcast ex of head (q>>1) from the lane in the same half-warp that holds it
    int srcLane = (t & 16) | (q >> 1);
    float exv = __shfl_sync(0xffffffffu, ex, srcLane);
    if (valid) {
        const float4 h4 = *(const float4*)&g_h[(long)s * OUTD + 4 * q];
        redAddV4(&out[(long)d * OUTD + 4 * q],
                 exv * h4.x, exv * h4.y, exv * h4.z, exv * h4.w);
    }
}

// ---------------- kernel 4: normalize + bias + relu (in place) ----------------
__global__ void k4_epilogue(float* __restrict__ out,
                            const float* __restrict__ bias,
                            int total4) { // N*16 float4s
    int t = blockIdx.x * blockDim.x + threadIdx.x;
    if (t >= total4) return;
    int n = t >> 4;
    int q = t & 15;
    int head = q >> 1;
    float4 v = ((float4*)out)[t];
    float den = g_den[n * HHEADS + head] + 1e-16f;
    float inv = 1.0f / den;
    float4 b = ((const float4*)bias)[q];
    v.x = fmaxf(fmaf(v.x, inv, b.x), 0.0f);
    v.y = fmaxf(fmaf(v.y, inv, b.y), 0.0f);
    v.z = fmaxf(fmaf(v.z, inv, b.z), 0.0f);
    v.w = fmaxf(fmaf(v.w, inv, b.w), 0.0f);
    ((float4*)out)[t] = v;
}

// ---------------- launch ----------------
extern "C" void kernel_launch(void* const* d_in, const int* in_sizes, int n_in,
                              void* d_out, int out_size) {
    const float* x     = (const float*)d_in[0];
    const int*   ei    = (const int*)d_in[1];
    const float* W     = (const float*)d_in[2];
    const float* att_s = (const float*)d_in[3];
    const float* att_d = (const float*)d_in[4];
    const float* bias  = (const float*)d_in[5];
    float* out = (float*)d_out;

    int N = in_sizes[0] / FEAT;
    int E = in_sizes[1] / 2;
    int Etot = E + N;

    k1_gemm_att<<<(N + 15) / 16, 128>>>(x, W, att_s, att_d, out, N);
    k2_max<<<(Etot + 255) / 256, 256>>>(ei, E, Etot);
    k3_accum<<<(Etot + 15) / 16, 256>>>(ei, out, E, Etot);
    k4_epilogue<<<(N * 16 + 255) / 256, 256>>>(out, bias, N * 16);
}

// round 3
// speedup vs baseline: 1.1692x; 1.1692x over previous
#include <cuda_runtime.h>
#include <math.h>

#define NMAX 100000
#define HHEADS 8
#define FEAT 128
#define OUTD 64   // H*C

// ---------------- device scratch (no allocations allowed) ----------------
__device__ float g_h[NMAX * OUTD];     // transformed features  [N,64]
__device__ float g_as[NMAX * HHEADS];  // a_src  [N,8]
__device__ float g_ad[NMAX * HHEADS];  // a_dst  [N,8]
__device__ float g_den[NMAX * HHEADS]; // segment sum  [N,8]

// ---------------- helpers ----------------
__device__ __forceinline__ void redAddV4(float* addr, float a, float b, float c, float d) {
    asm volatile("red.global.add.v4.f32 [%0], {%1, %2, %3, %4};"
                 :: "l"(addr), "f"(a), "f"(b), "f"(c), "f"(d) : "memory");
}
__device__ __forceinline__ void redAddF(float* addr, float a) {
    asm volatile("red.global.add.f32 [%0], %1;" :: "l"(addr), "f"(a) : "memory");
}

// ---------------- kernel 1: GEMM + attention logits + init ----------------
// 128 threads per block, 16 nodes per block, 8 threads per node (one head each).
__global__ void k1_gemm_att(const float* __restrict__ x,
                            const float* __restrict__ W,
                            const float* __restrict__ att_s,
                            const float* __restrict__ att_d,
                            float* __restrict__ out,
                            int N) {
    __shared__ float Ws[FEAT * OUTD];     // 32 KB
    __shared__ float xs[16][FEAT + 1];    // padded rows

    int t = threadIdx.x; // 0..127
    const float4* W4 = (const float4*)W;
    float4* Ws4 = (float4*)Ws;
    #pragma unroll
    for (int i = 0; i < 16; i++) {
        Ws4[t + 128 * i] = W4[t + 128 * i];
    }
    int node0 = blockIdx.x * 16;
    for (int i = t; i < 16 * FEAT; i += 128) {
        int nn = i >> 7;
        int kk = i & 127;
        int gn = node0 + nn;
        xs[nn][kk] = (gn < N) ? x[(long)gn * FEAT + kk] : 0.0f;
    }
    __syncthreads();

    int node = t >> 3;
    int head = t & 7;
    int gn = node0 + node;
    if (gn >= N) return;

    float acc[8];
    #pragma unroll
    for (int c = 0; c < 8; c++) acc[c] = 0.0f;

    const float* xrow = xs[node];
    #pragma unroll 4
    for (int k = 0; k < FEAT; k++) {
        float xv = xrow[k];
        const float4 w0 = *(const float4*)&Ws[k * OUTD + head * 8];
        const float4 w1 = *(const float4*)&Ws[k * OUTD + head * 8 + 4];
        acc[0] = fmaf(xv, w0.x, acc[0]);
        acc[1] = fmaf(xv, w0.y, acc[1]);
        acc[2] = fmaf(xv, w0.z, acc[2]);
        acc[3] = fmaf(xv, w0.w, acc[3]);
        acc[4] = fmaf(xv, w1.x, acc[4]);
        acc[5] = fmaf(xv, w1.y, acc[5]);
        acc[6] = fmaf(xv, w1.z, acc[6]);
        acc[7] = fmaf(xv, w1.w, acc[7]);
    }

    float as = 0.0f, ad = 0.0f;
    #pragma unroll
    for (int c = 0; c < 8; c++) {
        as = fmaf(acc[c], __ldg(&att_s[head * 8 + c]), as);
        ad = fmaf(acc[c], __ldg(&att_d[head * 8 + c]), ad);
    }

    long base = (long)gn * OUTD + head * 8;
    *(float4*)&g_h[base]     = make_float4(acc[0], acc[1], acc[2], acc[3]);
    *(float4*)&g_h[base + 4] = make_float4(acc[4], acc[5], acc[6], acc[7]);
    g_as[gn * HHEADS + head] = as;
    g_ad[gn * HHEADS + head] = ad;
    g_den[gn * HHEADS + head] = 0.0f;
    float4 z = make_float4(0.f, 0.f, 0.f, 0.f);
    *(float4*)&out[base] = z;
    *(float4*)&out[base + 4] = z;
}

// ---------------- kernel 3: exp + denom + unnormalized message scatter ----------------
// No max subtraction: softmax is shift-invariant and e is far from fp32 overflow.
// 16 lanes (half-warp) per edge; 256 threads -> 16 edges per block.
__global__ void k3_accum(const int* __restrict__ ei,
                         float* __restrict__ out,
                         int E, int Etot) {
    int t = threadIdx.x;
    int eid = blockIdx.x * 16 + (t >> 4);
    bool valid = (eid < Etot);
    int s = 0, d = 0;
    if (valid) {
        if (eid < E) {
            s = __ldg(&ei[eid]);
            d = __ldg(&ei[E + eid]);
        } else {
            s = d = eid - E;
        }
    }
    int q = t & 15;
    float ex = 0.0f;
    if (valid && q < 8) {
        float e = g_as[s * HHEADS + q] + g_ad[d * HHEADS + q];
        e = (e > 0.0f) ? e : 0.2f * e;
        ex = __expf(e);
        redAddF(&g_den[d * HHEADS + q], ex);
    }
    // broadcast ex of head (q>>1) from the lane in the same half-warp that holds it
    int srcLane = (t & 16) | (q >> 1);
    float exv = __shfl_sync(0xffffffffu, ex, srcLane);
    if (valid) {
        const float4 h4 = *(const float4*)&g_h[(long)s * OUTD + 4 * q];
        redAddV4(&out[(long)d * OUTD + 4 * q],
                 exv * h4.x, exv * h4.y, exv * h4.z, exv * h4.w);
    }
}

// ---------------- kernel 4: normalize + bias + relu (in place) ----------------
__global__ void k4_epilogue(float* __restrict__ out,
                            const float* __restrict__ bias,
                            int total4) { // N*16 float4s
    int t = blockIdx.x * blockDim.x + threadIdx.x;
    if (t >= total4) return;
    int n = t >> 4;
    int q = t & 15;
    int head = q >> 1;
    float4 v = ((float4*)out)[t];
    float den = g_den[n * HHEADS + head] + 1e-16f;
    float inv = 1.0f / den;
    float4 b = ((const float4*)bias)[q];
    v.x = fmaxf(fmaf(v.x, inv, b.x), 0.0f);
    v.y = fmaxf(fmaf(v.y, inv, b.y), 0.0f);
    v.z = fmaxf(fmaf(v.z, inv, b.z), 0.0f);
    v.w = fmaxf(fmaf(v.w, inv, b.w), 0.0f);
    ((float4*)out)[t] = v;
}

// ---------------- launch ----------------
extern "C" void kernel_launch(void* const* d_in, const int* in_sizes, int n_in,
                              void* d_out, int out_size) {
    const float* x     = (const float*)d_in[0];
    const int*   ei    = (const int*)d_in[1];
    const float* W     = (const float*)d_in[2];
    const float* att_s = (const float*)d_in[3];
    const float* att_d = (const float*)d_in[4];
    const float* bias  = (const float*)d_in[5];
    float* out = (float*)d_out;

    int N = in_sizes[0] / FEAT;
    int E = in_sizes[1] / 2;
    int Etot = E + N;

    k1_gemm_att<<<(N + 15) / 16, 128>>>(x, W, att_s, att_d, out, N);
    k3_accum<<<(Etot + 15) / 16, 256>>>(ei, out, E, Etot);
    k4_epilogue<<<(N * 16 + 255) / 256, 256>>>(out, bias, N * 16);
}

// round 4
// speedup vs baseline: 2.2482x; 1.9228x over previous
#include <cuda_runtime.h>
#include <math.h>

#define NMAX 100000
#define HHEADS 8
#define FEAT 128
#define OUTD 64   // H*C
#define BN 64     // nodes per block (k1)
#define KC 32     // k-chunk

// ---------------- device scratch ----------------
__device__ float g_h[NMAX * OUTD];     // transformed features  [N,64]
__device__ float g_as[NMAX * HHEADS];  // a_src  [N,8]
__device__ float g_ad[NMAX * HHEADS];  // a_dst  [N,8]
__device__ float g_den[NMAX * HHEADS]; // segment sum  [N,8]

// ---------------- helpers ----------------
__device__ __forceinline__ void redAddV4(float* addr, float a, float b, float c, float d) {
    asm volatile("red.global.add.v4.f32 [%0], {%1, %2, %3, %4};"
                 :: "l"(addr), "f"(a), "f"(b), "f"(c), "f"(d) : "memory");
}
__device__ __forceinline__ void redAddF(float* addr, float a) {
    asm volatile("red.global.add.f32 [%0], %1;" :: "l"(addr), "f"(a) : "memory");
}

// ---------------- kernel 1: register-tiled GEMM + logits + init ----------------
// 256 threads; block tile 64 nodes x 64 channels; thread tile 4x4.
__global__ __launch_bounds__(256) void k1_gemm_att(
        const float* __restrict__ x,
        const float* __restrict__ W,
        const float* __restrict__ att_s,
        const float* __restrict__ att_d,
        float* __restrict__ out,
        int N) {
    __shared__ float Ws[FEAT][OUTD];      // 32 KB  [k][ch]
    __shared__ float xs[KC][BN + 4];      // 8.5 KB [k][node], stride 68 (16B aligned)

    int t = threadIdx.x;                  // 0..255
    int node0 = blockIdx.x * BN;
    int tx = t & 15;                      // channel group: channels tx*4..tx*4+3
    int ty = t >> 4;                      // node group:   nodes   ty*4..ty*4+3 (rel)

    // cooperative load of W (128x64 = 2048 float4)
    {
        const float4* W4 = (const float4*)W;
        float4* Ws4 = (float4*)&Ws[0][0];
        #pragma unroll
        for (int i = 0; i < 8; i++) Ws4[t + 256 * i] = W4[t + 256 * i];
    }

    float acc[4][4];
    #pragma unroll
    for (int i = 0; i < 4; i++)
        #pragma unroll
        for (int j = 0; j < 4; j++) acc[i][j] = 0.0f;

    for (int kc = 0; kc < FEAT; kc += KC) {
        __syncthreads();
        // stage x chunk transposed: 64 rows x 8 float4 = 512 float4, 2 per thread
        #pragma unroll
        for (int i = 0; i < 2; i++) {
            int idx = t + 256 * i;       // 0..511
            int row = idx >> 3;          // node 0..63
            int kq  = idx & 7;           // float4 within chunk
            int gn = node0 + row;
            float4 v = make_float4(0.f, 0.f, 0.f, 0.f);
            if (gn < N) v = *(const float4*)&x[(long)gn * FEAT + kc + kq * 4];
            xs[kq * 4 + 0][row] = v.x;
            xs[kq * 4 + 1][row] = v.y;
            xs[kq * 4 + 2][row] = v.z;
            xs[kq * 4 + 3][row] = v.w;
        }
        __syncthreads();

        #pragma unroll
        for (int kk = 0; kk < KC; kk++) {
            float4 wv = *(const float4*)&Ws[kc + kk][tx * 4];
            float4 xv = *(const float4*)&xs[kk][ty * 4];
            acc[0][0] = fmaf(xv.x, wv.x, acc[0][0]);
            acc[0][1] = fmaf(xv.x, wv.y, acc[0][1]);
            acc[0][2] = fmaf(xv.x, wv.z, acc[0][2]);
            acc[0][3] = fmaf(xv.x, wv.w, acc[0][3]);
            acc[1][0] = fmaf(xv.y, wv.x, acc[1][0]);
            acc[1][1] = fmaf(xv.y, wv.y, acc[1][1]);
            acc[1][2] = fmaf(xv.y, wv.z, acc[1][2]);
            acc[1][3] = fmaf(xv.y, wv.w, acc[1][3]);
            acc[2][0] = fmaf(xv.z, wv.x, acc[2][0]);
            acc[2][1] = fmaf(xv.z, wv.y, acc[2][1]);
            acc[2][2] = fmaf(xv.z, wv.z, acc[2][2]);
            acc[2][3] = fmaf(xv.z, wv.w, acc[2][3]);
            acc[3][0] = fmaf(xv.w, wv.x, acc[3][0]);
            acc[3][1] = fmaf(xv.w, wv.y, acc[3][1]);
            acc[3][2] = fmaf(xv.w, wv.z, acc[3][2]);
            acc[3][3] = fmaf(xv.w, wv.w, acc[3][3]);
        }
    }

    // epilogue: write h, zero out/g_den, compute logits via pair shuffle
    const float4 av_s = *(const float4*)&att_s[tx * 4];
    const float4 av_d = *(const float4*)&att_d[tx * 4];
    int head = tx >> 1;
    float4 z = make_float4(0.f, 0.f, 0.f, 0.f);

    #pragma unroll
    for (int i = 0; i < 4; i++) {
        int node = node0 + ty * 4 + i;
        float4 h = make_float4(acc[i][0], acc[i][1], acc[i][2], acc[i][3]);
        float psrc = h.x * av_s.x + h.y * av_s.y + h.z * av_s.z + h.w * av_s.w;
        float pdst = h.x * av_d.x + h.y * av_d.y + h.z * av_d.z + h.w * av_d.w;
        psrc += __shfl_xor_sync(0xffffffffu, psrc, 1);
        pdst += __shfl_xor_sync(0xffffffffu, pdst, 1);
        if (node < N) {
            long base = (long)node * OUTD + tx * 4;
            *(float4*)&g_h[base] = h;
            *(float4*)&out[base] = z;
            if ((tx & 1) == 0) {
                g_as[node * HHEADS + head] = psrc;
                g_ad[node * HHEADS + head] = pdst;
                g_den[node * HHEADS + head] = 0.0f;
            }
        }
    }
}

// ---------------- kernel 3: exp + denom + unnormalized message scatter ----------------
__global__ void k3_accum(const int* __restrict__ ei,
                         float* __restrict__ out,
                         int E, int Etot) {
    int t = threadIdx.x;
    int eid = blockIdx.x * 16 + (t >> 4);
    bool valid = (eid < Etot);
    int s = 0, d = 0;
    if (valid) {
        if (eid < E) {
            s = __ldg(&ei[eid]);
            d = __ldg(&ei[E + eid]);
        } else {
            s = d = eid - E;
        }
    }
    int q = t & 15;
    float ex = 0.0f;
    if (valid && q < 8) {
        float e = g_as[s * HHEADS + q] + g_ad[d * HHEADS + q];
        e = (e > 0.0f) ? e : 0.2f * e;
        ex = __expf(e);
        redAddF(&g_den[d * HHEADS + q], ex);
    }
    int srcLane = (t & 16) | (q >> 1);
    float exv = __shfl_sync(0xffffffffu, ex, srcLane);
    if (valid) {
        const float4 h4 = *(const float4*)&g_h[(long)s * OUTD + 4 * q];
        redAddV4(&out[(long)d * OUTD + 4 * q],
                 exv * h4.x, exv * h4.y, exv * h4.z, exv * h4.w);
    }
}

// ---------------- kernel 4: normalize + bias + relu ----------------
__global__ void k4_epilogue(float* __restrict__ out,
                            const float* __restrict__ bias,
                            int total4) {
    int t = blockIdx.x * blockDim.x + threadIdx.x;
    if (t >= total4) return;
    int n = t >> 4;
    int q = t & 15;
    int head = q >> 1;
    float4 v = ((float4*)out)[t];
    float den = g_den[n * HHEADS + head] + 1e-16f;
    float inv = 1.0f / den;
    float4 b = ((const float4*)bias)[q];
    v.x = fmaxf(fmaf(v.x, inv, b.x), 0.0f);
    v.y = fmaxf(fmaf(v.y, inv, b.y), 0.0f);
    v.z = fmaxf(fmaf(v.z, inv, b.z), 0.0f);
    v.w = fmaxf(fmaf(v.w, inv, b.w), 0.0f);
    ((float4*)out)[t] = v;
}

// ---------------- launch ----------------
extern "C" void kernel_launch(void* const* d_in, const int* in_sizes, int n_in,
                              void* d_out, int out_size) {
    const float* x     = (const float*)d_in[0];
    const int*   ei    = (const int*)d_in[1];
    const float* W     = (const float*)d_in[2];
    const float* att_s = (const float*)d_in[3];
    const float* att_d = (const float*)d_in[4];
    const float* bias  = (const float*)d_in[5];
    float* out = (float*)d_out;

    int N = in_sizes[0] / FEAT;
    int E = in_sizes[1] / 2;
    int Etot = E + N;

    k1_gemm_att<<<(N + BN - 1) / BN, 256>>>(x, W, att_s, att_d, out, N);
    k3_accum<<<(Etot + 15) / 16, 256>>>(ei, out, E, Etot);
    k4_epilogue<<<(N * 16 + 255) / 256, 256>>>(out, bias, N * 16);
}

// round 5
// speedup vs baseline: 2.4817x; 1.1039x over previous
#include <cuda_runtime.h>
#include <math.h>

#define NMAX 100000
#define EMAX 1600000
#define HHEADS 8
#define FEAT 128
#define OUTD 64   // H*C
#define BN 64     // nodes per block (k1)
#define KC 32     // k-chunk
#define NB_MAX 128

// ---------------- device scratch ----------------
__device__ float g_h[NMAX * OUTD];       // transformed features  [N,64]
__device__ float g_as[NMAX * HHEADS];    // a_src  [N,8]
__device__ float g_ad[NMAX * HHEADS];    // a_dst  [N,8]
__device__ int   g_deg[NMAX];            // in-degree (incl self loop)
__device__ int   g_off[NMAX + 1];        // CSR offsets
__device__ int   g_cur[NMAX];            // scatter cursors
__device__ int   g_ssrc[EMAX + NMAX];    // src ids sorted by dst
__device__ int   g_bsum[NB_MAX];         // scan partials
__device__ int   g_bscan[NB_MAX];        // scanned partials (exclusive)

// ---------------- kernel 1: register-tiled GEMM + logits + deg init ----------------
// 256 threads; block tile 64 nodes x 64 channels; thread tile 4x4.
__global__ __launch_bounds__(256) void k1_gemm_att(
        const float* __restrict__ x,
        const float* __restrict__ W,
        const float* __restrict__ att_s,
        const float* __restrict__ att_d,
        int N) {
    __shared__ float Ws[FEAT][OUTD];      // 32 KB  [k][ch]
    __shared__ float xs[KC][BN + 4];      // [k][node]

    int t = threadIdx.x;                  // 0..255
    int node0 = blockIdx.x * BN;
    int tx = t & 15;                      // channel group
    int ty = t >> 4;                      // node group

    if (t < BN && node0 + t < N) g_deg[node0 + t] = 1;  // self loop counts

    {
        const float4* W4 = (const float4*)W;
        float4* Ws4 = (float4*)&Ws[0][0];
        #pragma unroll
        for (int i = 0; i < 8; i++) Ws4[t + 256 * i] = W4[t + 256 * i];
    }

    float acc[4][4];
    #pragma unroll
    for (int i = 0; i < 4; i++)
        #pragma unroll
        for (int j = 0; j < 4; j++) acc[i][j] = 0.0f;

    for (int kc = 0; kc < FEAT; kc += KC) {
        __syncthreads();
        #pragma unroll
        for (int i = 0; i < 2; i++) {
            int idx = t + 256 * i;       // 0..511
            int row = idx >> 3;
            int kq  = idx & 7;
            int gn = node0 + row;
            float4 v = make_float4(0.f, 0.f, 0.f, 0.f);
            if (gn < N) v = *(const float4*)&x[(long)gn * FEAT + kc + kq * 4];
            xs[kq * 4 + 0][row] = v.x;
            xs[kq * 4 + 1][row] = v.y;
            xs[kq * 4 + 2][row] = v.z;
            xs[kq * 4 + 3][row] = v.w;
        }
        __syncthreads();

        #pragma unroll
        for (int kk = 0; kk < KC; kk++) {
            float4 wv = *(const float4*)&Ws[kc + kk][tx * 4];
            float4 xv = *(const float4*)&xs[kk][ty * 4];
            acc[0][0] = fmaf(xv.x, wv.x, acc[0][0]);
            acc[0][1] = fmaf(xv.x, wv.y, acc[0][1]);
            acc[0][2] = fmaf(xv.x, wv.z, acc[0][2]);
            acc[0][3] = fmaf(xv.x, wv.w, acc[0][3]);
            acc[1][0] = fmaf(xv.y, wv.x, acc[1][0]);
            acc[1][1] = fmaf(xv.y, wv.y, acc[1][1]);
            acc[1][2] = fmaf(xv.y, wv.z, acc[1][2]);
            acc[1][3] = fmaf(xv.y, wv.w, acc[1][3]);
            acc[2][0] = fmaf(xv.z, wv.x, acc[2][0]);
            acc[2][1] = fmaf(xv.z, wv.y, acc[2][1]);
            acc[2][2] = fmaf(xv.z, wv.z, acc[2][2]);
            acc[2][3] = fmaf(xv.z, wv.w, acc[2][3]);
            acc[3][0] = fmaf(xv.w, wv.x, acc[3][0]);
            acc[3][1] = fmaf(xv.w, wv.y, acc[3][1]);
            acc[3][2] = fmaf(xv.w, wv.z, acc[3][2]);
            acc[3][3] = fmaf(xv.w, wv.w, acc[3][3]);
        }
    }

    const float4 av_s = *(const float4*)&att_s[tx * 4];
    const float4 av_d = *(const float4*)&att_d[tx * 4];
    int head = tx >> 1;

    #pragma unroll
    for (int i = 0; i < 4; i++) {
        int node = node0 + ty * 4 + i;
        float4 h = make_float4(acc[i][0], acc[i][1], acc[i][2], acc[i][3]);
        float psrc = h.x * av_s.x + h.y * av_s.y + h.z * av_s.z + h.w * av_s.w;
        float pdst = h.x * av_d.x + h.y * av_d.y + h.z * av_d.z + h.w * av_d.w;
        psrc += __shfl_xor_sync(0xffffffffu, psrc, 1);
        pdst += __shfl_xor_sync(0xffffffffu, pdst, 1);
        if (node < N) {
            *(float4*)&g_h[(long)node * OUTD + tx * 4] = h;
            if ((tx & 1) == 0) {
                g_as[node * HHEADS + head] = psrc;
                g_ad[node * HHEADS + head] = pdst;
            }
        }
    }
}

// ---------------- histogram of dst ----------------
__global__ void k2a_hist(const int* __restrict__ ei, int E) {
    int t = blockIdx.x * blockDim.x + threadIdx.x;
    if (t >= E) return;
    atomicAdd(&g_deg[__ldg(&ei[E + t])], 1);
}

// ---------------- scan part A: per-block sums ----------------
__global__ __launch_bounds__(1024) void kA_bsum(int N) {
    int t = threadIdx.x;
    int idx = blockIdx.x * 1024 + t;
    int v = (idx < N) ? g_deg[idx] : 0;
    #pragma unroll
    for (int o = 16; o; o >>= 1) v += __shfl_down_sync(0xffffffffu, v, o);
    __shared__ int ws[32];
    int lane = t & 31, wid = t >> 5;
    if (lane == 0) ws[wid] = v;
    __syncthreads();
    if (wid == 0) {
        v = ws[lane];
        #pragma unroll
        for (int o = 16; o; o >>= 1) v += __shfl_down_sync(0xffffffffu, v, o);
        if (lane == 0) g_bsum[blockIdx.x] = v;
    }
}

// ---------------- scan part B: scan block sums (single block, 128 thr) ----------------
__global__ void kB_bscan(int NB) {
    int t = threadIdx.x;       // 0..127
    int lane = t & 31, wid = t >> 5;
    int v = (t < NB) ? g_bsum[t] : 0;
    int orig = v;
    #pragma unroll
    for (int o = 1; o < 32; o <<= 1) {
        int u = __shfl_up_sync(0xffffffffu, v, o);
        if (lane >= o) v += u;
    }
    __shared__ int s[4];
    if (lane == 31) s[wid] = v;
    __syncthreads();
    int add = 0;
    for (int w = 0; w < wid; w++) add += s[w];
    v += add;
    if (t < NB) g_bscan[t] = v - orig;   // exclusive
}

// ---------------- scan part C: per-block exclusive scan + offsets + cursors ----------------
__global__ __launch_bounds__(1024) void kC_offsets(int N) {
    int t = threadIdx.x;
    int idx = blockIdx.x * 1024 + t;
    int lane = t & 31, wid = t >> 5;
    int v = (idx < N) ? g_deg[idx] : 0;
    int orig = v;
    #pragma unroll
    for (int o = 1; o < 32; o <<= 1) {
        int u = __shfl_up_sync(0xffffffffu, v, o);
        if (lane >= o) v += u;
    }
    __shared__ int ws[32];
    if (lane == 31) ws[wid] = v;
    __syncthreads();
    if (wid == 0) {
        int u = ws[lane];
        #pragma unroll
        for (int o = 1; o < 32; o <<= 1) {
            int uu = __shfl_up_sync(0xffffffffu, u, o);
            if (lane >= o) u += uu;
        }
        ws[lane] = u;
    }
    __syncthreads();
    int base = (wid > 0) ? ws[wid - 1] : 0;
    int excl = v - orig + base + g_bscan[blockIdx.x];
    if (idx < N) {
        g_off[idx] = excl;
        g_cur[idx] = excl;
        if (idx == N - 1) g_off[N] = excl + orig;
    }
}

// ---------------- scatter edges by dst ----------------
__global__ void k2c_scatter(const int* __restrict__ ei, int E, int Etot) {
    int t = blockIdx.x * blockDim.x + threadIdx.x;
    if (t >= Etot) return;
    int s, d;
    if (t < E) {
        s = __ldg(&ei[t]);
        d = __ldg(&ei[E + t]);
    } else {
        s = d = t - E;
    }
    int pos = atomicAdd(&g_cur[d], 1);
    g_ssrc[pos] = s;
}

// ---------------- CSR reduce: softmax-weighted aggregation, bias, relu ----------------
// one warp per dst node; two half-warps each handle one incoming edge per iter.
__global__ __launch_bounds__(256) void k3_reduce(
        float* __restrict__ out,
        const float* __restrict__ bias,
        int N) {
    int lane = threadIdx.x & 31;
    int n = blockIdx.x * 8 + (threadIdx.x >> 5);
    if (n >= N) return;
    int q = lane & 15;
    int half = lane >> 4;

    float ad = (q < 8) ? g_ad[n * HHEADS + q] : 0.0f;
    int off = g_off[n];
    int end = g_off[n + 1];

    float a0 = 0.f, a1 = 0.f, a2 = 0.f, a3 = 0.f, accden = 0.f;

    for (int i0 = off; i0 < end; i0 += 2) {
        int i = i0 + half;
        bool act = (i < end);
        int s = g_ssrc[act ? i : end - 1];
        float ex = 0.0f;
        if (q < 8) {
            float e = g_as[s * HHEADS + q] + ad;
            e = (e > 0.0f) ? e : 0.2f * e;
            ex = act ? __expf(e) : 0.0f;
            accden += ex;
        }
        float exv = __shfl_sync(0xffffffffu, ex, (half << 4) | (q >> 1));
        float4 h4 = *(const float4*)&g_h[(long)s * OUTD + 4 * q];
        a0 = fmaf(exv, h4.x, a0);
        a1 = fmaf(exv, h4.y, a1);
        a2 = fmaf(exv, h4.z, a2);
        a3 = fmaf(exv, h4.w, a3);
    }

    // merge the two halves
    a0 += __shfl_down_sync(0xffffffffu, a0, 16);
    a1 += __shfl_down_sync(0xffffffffu, a1, 16);
    a2 += __shfl_down_sync(0xffffffffu, a2, 16);
    a3 += __shfl_down_sync(0xffffffffu, a3, 16);
    accden += __shfl_down_sync(0xffffffffu, accden, 16);
    float den = __shfl_sync(0xffffffffu, accden, q >> 1);  // head of lane q

    if (lane < 16) {
        float inv = 1.0f / (den + 1e-16f);
        float4 b = *(const float4*)&bias[4 * q];
        float4 v;
        v.x = fmaxf(fmaf(a0, inv, b.x), 0.0f);
        v.y = fmaxf(fmaf(a1, inv, b.y), 0.0f);
        v.z = fmaxf(fmaf(a2, inv, b.z), 0.0f);
        v.w = fmaxf(fmaf(a3, inv, b.w), 0.0f);
        *(float4*)&out[(long)n * OUTD + 4 * q] = v;
    }
}

// ---------------- launch ----------------
extern "C" void kernel_launch(void* const* d_in, const int* in_sizes, int n_in,
                              void* d_out, int out_size) {
    const float* x     = (const float*)d_in[0];
    const int*   ei    = (const int*)d_in[1];
    const float* W     = (const float*)d_in[2];
    const float* att_s = (const float*)d_in[3];
    const float* att_d = (const float*)d_in[4];
    const float* bias  = (const float*)d_in[5];
    float* out = (float*)d_out;

    int N = in_sizes[0] / FEAT;
    int E = in_sizes[1] / 2;
    int Etot = E + N;
    int NB = (N + 1023) / 1024;

    k1_gemm_att<<<(N + BN - 1) / BN, 256>>>(x, W, att_s, att_d, N);
    k2a_hist<<<(E + 255) / 256, 256>>>(ei, E);
    kA_bsum<<<NB, 1024>>>(N);
    kB_bscan<<<1, 128>>>(NB);
    kC_offsets<<<NB, 1024>>>(N);
    k2c_scatter<<<(Etot + 255) / 256, 256>>>(ei, E, Etot);
    k3_reduce<<<(N + 7) / 8, 256>>>(out, bias, N);
}